// round 16
// baseline (speedup 1.0000x reference)
#include <cuda_runtime.h>
#include <cuda_bf16.h>
#include <cstdint>

#define LOG2E 1.4426950408889634f
#define NPTS 4096

// mma.sync m16n8k16 bf16 (row.col), f32 accum.
#define MMA16816(c, a, b0v, b1v)                                               \
    asm("mma.sync.aligned.m16n8k16.row.col.f32.bf16.bf16.f32 "                 \
        "{%0,%1,%2,%3}, {%4,%5,%6,%7}, {%8,%9}, {%0,%1,%2,%3};"                \
        : "+f"((c)[0]), "+f"((c)[1]), "+f"((c)[2]), "+f"((c)[3])               \
        : "r"((a)[0]), "r"((a)[1]), "r"((a)[2]), "r"((a)[3]),                  \
          "r"(b0v), "r"(b1v))

#define EX2(v) asm("ex2.approx.ftz.f32 %0, %0;" : "+f"(v))

// Pre-packed operands in fragment order (8B per lane entry):
// Ag: [it][wg][mt][ks][pq][lane]  -> 32 * 1536 uint2
// Bg: [jt][h][k][ks][e][lane]     -> 32 * 1536 uint2
__device__ uint2 Ag[32 * 1536];
__device__ uint2 Bg[32 * 1536];
__device__ float CSg[NPTS];
__device__ float DSg[NPTS];

__device__ __forceinline__ uint32_t pack_bf2(__nv_bfloat16 a, __nv_bfloat16 b) {
    __nv_bfloat162 t(a, b);
    return *reinterpret_cast<uint32_t*>(&t);
}

// ---- kernel 1: one-shot convert x/xx -> fragment-layout bf16 hi/lo scratch ----
__global__ void rbf_prep(const float* __restrict__ x,
                         const float* __restrict__ xx,
                         const float* __restrict__ scale_ff,
                         const float* __restrict__ var_ff) {
    __shared__ float SINV[17];
    const int tid = threadIdx.x;
    if (tid < 16) {
        SINV[tid] = 1.0f / log1pf(__expf(scale_ff[tid]));
    } else if (tid == 16) {
        SINV[16] = log2f(log1pf(__expf(var_ff[0])));
    }
    const int p = blockIdx.x * 256 + tid;          // 32 blocks x 256 = 8192
    const bool is_x = p < NPTS;
    const int row = is_x ? p : p - NPTS;
    const float4* rp = (const float4*)((is_x ? x : xx) + (size_t)row * 16);
    float4 ra = rp[0], rb = rp[1], rc = rp[2], rd = rp[3];
    __syncthreads();

    float vals[16] = {ra.x, ra.y, ra.z, ra.w, rb.x, rb.y, rb.z, rb.w,
                      rc.x, rc.y, rc.z, rc.w, rd.x, rd.y, rd.z, rd.w};
    uint32_t hp[8], lp[8];
    float s2 = 0.0f;
#pragma unroll
    for (int d = 0; d < 16; d += 2) {
        float u0 = vals[d] * SINV[d];
        float u1 = vals[d + 1] * SINV[d + 1];
        s2 = fmaf(u0, u0, fmaf(u1, u1, s2));
        float w0 = is_x ? u0 : (LOG2E * u0);
        float w1 = is_x ? u1 : (LOG2E * u1);
        __nv_bfloat16 h0 = __float2bfloat16_rn(w0);
        __nv_bfloat16 h1 = __float2bfloat16_rn(w1);
        __nv_bfloat16 l0 = __float2bfloat16_rn(w0 - __bfloat162float(h0));
        __nv_bfloat16 l1 = __float2bfloat16_rn(w1 - __bfloat162float(h1));
        hp[d >> 1] = pack_bf2(h0, h1);
        lp[d >> 1] = pack_bf2(l0, l1);
    }

    if (is_x) {
        CSg[row] = -0.5f * LOG2E * s2;
        const int it = row >> 7, i0 = row & 127;
        const int wg = i0 >> 5, r = i0 & 31;
        const int mt = r >> 4, pq = (r >> 3) & 1, qr = r & 7;
        // A chunks: ks0=uh, ks1=ul, ks2=uh
#pragma unroll
        for (int ks = 0; ks < 3; ks++) {
            const uint32_t* src = (ks == 1) ? lp : hp;
#pragma unroll
            for (int qc = 0; qc < 4; qc++) {
                Ag[((((it * 4 + wg) * 2 + mt) * 3 + ks) * 2 + pq) * 32 +
                   qr * 4 + qc] = make_uint2(src[qc], src[qc + 4]);
            }
        }
    } else {
        DSg[row] = -0.5f * LOG2E * s2 + SINV[16];
        const int jt = row >> 7, j0 = row & 127;
        const int h = j0 >> 6, j64 = j0 & 63;
        const int k = j64 >> 4, qcj = (j64 >> 2) & 3;
        const int m = (j64 >> 1) & 1, e = j64 & 1;
        const int qrb = 2 * qcj + e;               // fragment n-row within n8
        // B chunks: ks0=vh, ks1=vh, ks2=vl
#pragma unroll
        for (int ks = 0; ks < 3; ks++) {
            const uint32_t* src = (ks == 2) ? lp : hp;
#pragma unroll
            for (int qc = 0; qc < 4; qc++) {
                Bg[((((jt * 2 + h) * 4 + k) * 3 + ks) * 2 + m) * 32 +
                   qrb * 4 + qc] = make_uint2(src[qc], src[qc + 4]);
            }
        }
    }
}

// ---- kernel 2: barrier-free warp-independent GEMM + exp epilogue ----
// Unit = one 32x64 warp-tile; u = ((jt*2+h)*4+wg)*32+it so concurrent
// warps share B fragments (L1/L2 broadcast).
__global__ void __launch_bounds__(256) rbf_main(float* __restrict__ out) {
    const int lane = threadIdx.x & 31;
    const int qrow = lane >> 2, qcol = lane & 3;
    const int wgid = blockIdx.x * 8 + (threadIdx.x >> 5);
    const int nw = gridDim.x * 8;

    for (int u = wgid; u < 8192; u += nw) {
        const int it = u & 31;
        const int wg = (u >> 5) & 3;
        const int h  = (u >> 7) & 1;
        const int jt = u >> 8;

        // A fragments: 12 coalesced LDG.64
        uint32_t af[3][2][4];
        const uint2* Ab = Ag + it * 1536;
#pragma unroll
        for (int ks = 0; ks < 3; ks++) {
#pragma unroll
            for (int mt = 0; mt < 2; mt++) {
                uint2 pp = Ab[(((wg * 2 + mt) * 3 + ks) * 2 + 0) * 32 + lane];
                uint2 qq = Ab[(((wg * 2 + mt) * 3 + ks) * 2 + 1) * 32 + lane];
                af[ks][mt][0] = pp.x;
                af[ks][mt][1] = qq.x;
                af[ks][mt][2] = pp.y;
                af[ks][mt][3] = qq.y;
            }
        }
        const float* CSb = CSg + it * 128 + wg * 32 + qrow;
        float ci[4] = {CSb[0], CSb[8], CSb[16], CSb[24]};

        const uint2* Bb = Bg + (jt * 2 + h) * 768;
        const float* DJ = DSg + jt * 128 + h * 64 + qcol * 4;

#pragma unroll
        for (int k = 0; k < 4; k++) {
            float4 dj = *(const float4*)(DJ + 16 * k);
            uint2 b[3][2];
#pragma unroll
            for (int ks = 0; ks < 3; ks++) {
                b[ks][0] = Bb[((k * 3 + ks) * 2 + 0) * 32 + lane];
                b[ks][1] = Bb[((k * 3 + ks) * 2 + 1) * 32 + lane];
            }
            float a0[2][4], a1[2][4];
#pragma unroll
            for (int mt = 0; mt < 2; mt++) {
                a0[mt][0] = ci[2 * mt] + dj.x;
                a0[mt][1] = ci[2 * mt] + dj.y;
                a0[mt][2] = ci[2 * mt + 1] + dj.x;
                a0[mt][3] = ci[2 * mt + 1] + dj.y;
                a1[mt][0] = ci[2 * mt] + dj.z;
                a1[mt][1] = ci[2 * mt] + dj.w;
                a1[mt][2] = ci[2 * mt + 1] + dj.z;
                a1[mt][3] = ci[2 * mt + 1] + dj.w;
            }
#pragma unroll
            for (int ks = 0; ks < 3; ks++) {
                MMA16816(a0[0], af[ks][0], b[ks][0].x, b[ks][0].y);
                MMA16816(a0[1], af[ks][1], b[ks][0].x, b[ks][0].y);
                MMA16816(a1[0], af[ks][0], b[ks][1].x, b[ks][1].y);
                MMA16816(a1[1], af[ks][1], b[ks][1].x, b[ks][1].y);
            }
            const int col = jt * 128 + h * 64 + k * 16 + qcol * 4;
#pragma unroll
            for (int mt = 0; mt < 2; mt++) {
                float f0 = a0[mt][0], f1 = a0[mt][1];
                float f2 = a1[mt][0], f3 = a1[mt][1];
                float g0 = a0[mt][2], g1 = a0[mt][3];
                float g2 = a1[mt][2], g3 = a1[mt][3];
                EX2(f0); EX2(f1); EX2(f2); EX2(f3);
                EX2(g0); EX2(g1); EX2(g2); EX2(g3);
                const int r0 = it * 128 + wg * 32 + mt * 16 + qrow;
                *(float4*)&out[(size_t)r0 * NPTS + col] =
                    make_float4(f0, f1, f2, f3);
                *(float4*)&out[(size_t)(r0 + 8) * NPTS + col] =
                    make_float4(g0, g1, g2, g3);
            }
        }
    }
}

extern "C" void kernel_launch(void* const* d_in, const int* in_sizes, int n_in,
                              void* d_out, int out_size) {
    const float* x        = (const float*)d_in[0];
    const float* xx       = (const float*)d_in[1];
    const float* scale_ff = (const float*)d_in[2];
    const float* var_ff   = (const float*)d_in[3];
    float* out = (float*)d_out;

    int sms = 148;
    cudaDeviceGetAttribute(&sms, cudaDevAttrMultiProcessorCount, 0);

    rbf_prep<<<32, 256>>>(x, xx, scale_ff, var_ff);
    rbf_main<<<sms * 3, 256>>>(out);
}